// round 1
// baseline (speedup 1.0000x reference)
#include <cuda_runtime.h>
#include <cuda_bf16.h>
#include <math.h>

#define T_TOK 8192
#define DM 1024
#define DF 4096
#define NE 8

// ---------------- scratch (device globals; no allocation allowed) -------------
__device__ int   g_count[NE];
__device__ float g_prob_sum[NE];
__device__ int   g_tok[NE * T_TOK];            // token id per (expert, slot)
__device__ int   g_entry[T_TOK * 2];           // per token: two global row ids (e*T+slot)
__device__ float g_wgt[T_TOK * 2];             // per token: renormalized top-2 weights
__device__ float g_H[(size_t)NE * T_TOK * DF]; // intermediate relu(x W1 + b1)
__device__ float g_Y[(size_t)NE * T_TOK * DM]; // per-entry expert output

// ---------------- init: zero counters -----------------------------------------
__global__ void init_kernel() {
    int t = threadIdx.x;
    if (t < NE) { g_count[t] = 0; g_prob_sum[t] = 0.0f; }
}

// ---------------- router: 1 warp per token -------------------------------------
__global__ void router_kernel(const float* __restrict__ x,
                              const float* __restrict__ Wg,
                              const float* __restrict__ bg) {
    __shared__ float s_prob[NE];
    if (threadIdx.x < NE) s_prob[threadIdx.x] = 0.0f;
    __syncthreads();

    int warp = (blockIdx.x * blockDim.x + threadIdx.x) >> 5;
    int lane = threadIdx.x & 31;

    if (warp < T_TOK) {
        int t = warp;
        const float* xr = x + (size_t)t * DM;
        float acc[NE];
#pragma unroll
        for (int e = 0; e < NE; e++) acc[e] = 0.0f;
        for (int d = lane; d < DM; d += 32) {
            float xv = xr[d];
            const float* wr = Wg + d * NE;
#pragma unroll
            for (int e = 0; e < NE; e++) acc[e] += xv * wr[e];
        }
#pragma unroll
        for (int e = 0; e < NE; e++) {
            acc[e] += __shfl_down_sync(0xffffffffu, acc[e], 16);
            acc[e] += __shfl_down_sync(0xffffffffu, acc[e], 8);
            acc[e] += __shfl_down_sync(0xffffffffu, acc[e], 4);
            acc[e] += __shfl_down_sync(0xffffffffu, acc[e], 2);
            acc[e] += __shfl_down_sync(0xffffffffu, acc[e], 1);
        }
        if (lane == 0) {
            float p[NE];
            float mx = -1e30f;
#pragma unroll
            for (int e = 0; e < NE; e++) {
                p[e] = acc[e] + bg[e];
                mx = fmaxf(mx, p[e]);
            }
            float s = 0.0f;
#pragma unroll
            for (int e = 0; e < NE; e++) { p[e] = __expf(p[e] - mx); s += p[e]; }
            float inv = 1.0f / s;
#pragma unroll
            for (int e = 0; e < NE; e++) p[e] *= inv;

            // top-2 (lowest index wins ties, matching lax.top_k)
            int i0 = 0;
#pragma unroll
            for (int e = 1; e < NE; e++) if (p[e] > p[i0]) i0 = e;
            int i1 = (i0 == 0) ? 1 : 0;
#pragma unroll
            for (int e = 0; e < NE; e++) if (e != i0 && p[e] > p[i1]) i1 = e;

            float w0 = p[i0], w1 = p[i1];
            float winv = 1.0f / (w0 + w1);
            w0 *= winv; w1 *= winv;

            int s0 = atomicAdd(&g_count[i0], 1);
            int s1 = atomicAdd(&g_count[i1], 1);
            g_tok[i0 * T_TOK + s0] = t;
            g_tok[i1 * T_TOK + s1] = t;
            g_entry[t * 2 + 0] = i0 * T_TOK + s0;
            g_entry[t * 2 + 1] = i1 * T_TOK + s1;
            g_wgt[t * 2 + 0] = w0;
            g_wgt[t * 2 + 1] = w1;
#pragma unroll
            for (int e = 0; e < NE; e++) atomicAdd(&s_prob[e], p[e]);
        }
    }
    __syncthreads();
    if (threadIdx.x < NE) atomicAdd(&g_prob_sum[threadIdx.x], s_prob[threadIdx.x]);
}

// ---------------- pass 1: H = relu(Xg W1[e] + b1[e]) ---------------------------
// grid (DF/128, T/128, NE), block 256. classic 128x128 tile, 8x8 microtile.
__global__ __launch_bounds__(256, 2)
void ffn1_kernel(const float* __restrict__ x,
                 const float* __restrict__ W1,
                 const float* __restrict__ b1) {
    int e = blockIdx.z;
    int cnt = g_count[e];
    int m0 = blockIdx.y * 128;
    if (m0 >= cnt) return;
    int n0 = blockIdx.x * 128;

    __shared__ float As[8][132];
    __shared__ float Bs[8][132];
    __shared__ int rows[128];

    int tid = threadIdx.x;
    if (tid < 128) {
        int mi = m0 + tid;
        rows[tid] = g_tok[e * T_TOK + ((mi < cnt) ? mi : (cnt - 1))];
    }
    __syncthreads();

    float acc[8][8];
#pragma unroll
    for (int r = 0; r < 8; r++)
#pragma unroll
        for (int c = 0; c < 8; c++) acc[r][c] = 0.0f;

    const float* Bbase = W1 + (size_t)e * DM * DF + n0;
    int tx = tid & 15, ty = tid >> 4;

    for (int k0 = 0; k0 < DM; k0 += 8) {
#pragma unroll
        for (int r = 0; r < 4; r++) {
            int idx = tid + r * 256;
            int i = idx >> 3, k = idx & 7;
            As[k][i] = x[(size_t)rows[i] * DM + k0 + k];
        }
#pragma unroll
        for (int r = 0; r < 4; r++) {
            int idx = tid + r * 256;
            int k = idx >> 7, n = idx & 127;
            Bs[k][n] = Bbase[(size_t)(k0 + k) * DF + n];
        }
        __syncthreads();
#pragma unroll
        for (int kk = 0; kk < 8; kk++) {
            float a[8], b[8];
#pragma unroll
            for (int r = 0; r < 8; r++) a[r] = As[kk][ty * 8 + r];
#pragma unroll
            for (int c = 0; c < 8; c++) b[c] = Bs[kk][tx * 8 + c];
#pragma unroll
            for (int r = 0; r < 8; r++)
#pragma unroll
                for (int c = 0; c < 8; c++) acc[r][c] += a[r] * b[c];
        }
        __syncthreads();
    }

    const float* b1e = b1 + (size_t)e * DF + n0;
#pragma unroll
    for (int r = 0; r < 8; r++) {
        int mi = m0 + ty * 8 + r;
        if (mi < cnt) {
            size_t rowoff = ((size_t)e * T_TOK + mi) * DF + n0;
#pragma unroll
            for (int c = 0; c < 8; c++) {
                int n = tx * 8 + c;
                float v = acc[r][c] + b1e[n];
                g_H[rowoff + n] = v > 0.0f ? v : 0.0f;
            }
        }
    }
}

// ---------------- pass 2: Y = H W2[e] + b2[e] ----------------------------------
// grid (DM/128, T/128, NE), block 256.
__global__ __launch_bounds__(256, 2)
void ffn2_kernel(const float* __restrict__ W2,
                 const float* __restrict__ b2) {
    int e = blockIdx.z;
    int cnt = g_count[e];
    int m0 = blockIdx.y * 128;
    if (m0 >= cnt) return;
    int n0 = blockIdx.x * 128;

    __shared__ float As[8][132];
    __shared__ float Bs[8][132];

    int tid = threadIdx.x;
    float acc[8][8];
#pragma unroll
    for (int r = 0; r < 8; r++)
#pragma unroll
        for (int c = 0; c < 8; c++) acc[r][c] = 0.0f;

    const float* Abase = g_H + ((size_t)e * T_TOK + m0) * DF;
    const float* Bbase = W2 + (size_t)e * DF * DM + n0;
    int tx = tid & 15, ty = tid >> 4;

    for (int k0 = 0; k0 < DF; k0 += 8) {
#pragma unroll
        for (int r = 0; r < 4; r++) {
            int idx = tid + r * 256;
            int i = idx >> 3, k = idx & 7;
            int mi = m0 + i;
            // rows beyond cnt read duplicated valid row (masked at store)
            int isafe = (mi < cnt) ? i : (cnt - 1 - m0);
            As[k][i] = Abase[(size_t)isafe * DF + k0 + k];
        }
#pragma unroll
        for (int r = 0; r < 4; r++) {
            int idx = tid + r * 256;
            int k = idx >> 7, n = idx & 127;
            Bs[k][n] = Bbase[(size_t)(k0 + k) * DM + n];
        }
        __syncthreads();
#pragma unroll
        for (int kk = 0; kk < 8; kk++) {
            float a[8], b[8];
#pragma unroll
            for (int r = 0; r < 8; r++) a[r] = As[kk][ty * 8 + r];
#pragma unroll
            for (int c = 0; c < 8; c++) b[c] = Bs[kk][tx * 8 + c];
#pragma unroll
            for (int r = 0; r < 8; r++)
#pragma unroll
                for (int c = 0; c < 8; c++) acc[r][c] += a[r] * b[c];
        }
        __syncthreads();
    }

    const float* b2e = b2 + (size_t)e * DM + n0;
#pragma unroll
    for (int r = 0; r < 8; r++) {
        int mi = m0 + ty * 8 + r;
        if (mi < cnt) {
            size_t rowoff = ((size_t)e * T_TOK + mi) * DM + n0;
#pragma unroll
            for (int c = 0; c < 8; c++) {
                int n = tx * 8 + c;
                g_Y[rowoff + n] = acc[r][c] + b2e[n];
            }
        }
    }
}

// ---------------- combine: out[t] = w0*Y[e0] + w1*Y[e1] ------------------------
__global__ void combine_kernel(float* __restrict__ out) {
    int idx = blockIdx.x * blockDim.x + threadIdx.x;   // over T*DM/4
    int total = T_TOK * (DM / 4);
    if (idx >= total) return;
    int t = idx / (DM / 4);
    int d4 = idx % (DM / 4);
    int e0 = g_entry[t * 2 + 0];
    int e1 = g_entry[t * 2 + 1];
    float w0 = g_wgt[t * 2 + 0];
    float w1 = g_wgt[t * 2 + 1];
    const float4* y0 = (const float4*)(g_Y + (size_t)e0 * DM) + d4;
    const float4* y1 = (const float4*)(g_Y + (size_t)e1 * DM) + d4;
    float4 a = *y0, b = *y1;
    float4 o;
    o.x = w0 * a.x + w1 * b.x;
    o.y = w0 * a.y + w1 * b.y;
    o.z = w0 * a.z + w1 * b.z;
    o.w = w0 * a.w + w1 * b.w;
    ((float4*)out)[idx] = o;
}

// ---------------- loss: var(ddof=1) of per-expert mean prob --------------------
__global__ void loss_kernel(float* __restrict__ out) {
    if (threadIdx.x == 0 && blockIdx.x == 0) {
        float m[NE];
        float mu = 0.0f;
#pragma unroll
        for (int e = 0; e < NE; e++) {
            m[e] = g_prob_sum[e] / (float)T_TOK;
            mu += m[e];
        }
        mu /= (float)NE;
        float v = 0.0f;
#pragma unroll
        for (int e = 0; e < NE; e++) {
            float d = m[e] - mu;
            v += d * d;
        }
        v /= (float)(NE - 1);
        out[(size_t)T_TOK * DM] = v;
    }
}

// ---------------- launch ------------------------------------------------------
extern "C" void kernel_launch(void* const* d_in, const int* in_sizes, int n_in,
                              void* d_out, int out_size) {
    const float* x  = (const float*)d_in[0];
    const float* Wg = (const float*)d_in[1];
    const float* bg = (const float*)d_in[2];
    const float* W1 = (const float*)d_in[3];
    const float* b1 = (const float*)d_in[4];
    const float* W2 = (const float*)d_in[5];
    const float* b2 = (const float*)d_in[6];
    float* out = (float*)d_out;

    init_kernel<<<1, 32>>>();
    router_kernel<<<T_TOK / 8, 256>>>(x, Wg, bg);
    ffn1_kernel<<<dim3(DF / 128, T_TOK / 128, NE), 256>>>(x, W1, b1);
    ffn2_kernel<<<dim3(DM / 128, T_TOK / 128, NE), 256>>>(W2, b2);
    combine_kernel<<<(T_TOK * (DM / 4) + 255) / 256, 256>>>(out);
    loss_kernel<<<1, 1>>>(out);
}

// round 7
// speedup vs baseline: 1.8992x; 1.8992x over previous
#include <cuda_runtime.h>
#include <cuda_bf16.h>
#include <mma.h>
#include <math.h>
#include <stdint.h>

using namespace nvcuda;

#define T_TOK 8192
#define DM 1024
#define DF 4096
#define NE 8

// ---------------- scratch (device globals; no allocation allowed) -------------
__device__ int   g_count[NE];
__device__ float g_prob_sum[NE];
__device__ int   g_tok[NE * T_TOK];
__device__ int   g_entry[T_TOK * 2];
__device__ float g_wgt[T_TOK * 2];
__device__ float g_H[(size_t)NE * T_TOK * DF]; // fp32, same as proven round 1
__device__ float g_Y[(size_t)NE * T_TOK * DM]; // fp32, same as proven round 1

// ---------------- helpers ------------------------------------------------------
__device__ __forceinline__ void split2(float v, __nv_bfloat16& h, __nv_bfloat16& l) {
    h = __float2bfloat16(v);
    l = __float2bfloat16(v - __bfloat162float(h));
}

// load 8 consecutive fp32, split to 8 hi + 8 lo bf16, store 16B each to smem
__device__ __forceinline__ void split8_store(const float* __restrict__ src,
                                             char* dh, char* dl) {
    float4 v0 = *(const float4*)src;
    float4 v1 = *(const float4*)(src + 4);
    float vv[8] = {v0.x, v0.y, v0.z, v0.w, v1.x, v1.y, v1.z, v1.w};
    __align__(16) __nv_bfloat16 h[8];
    __align__(16) __nv_bfloat16 l[8];
#pragma unroll
    for (int i = 0; i < 8; i++) split2(vv[i], h[i], l[i]);
    *(uint4*)dh = *(const uint4*)h;
    *(uint4*)dl = *(const uint4*)l;
}

// ---------------- init ---------------------------------------------------------
__global__ void init_kernel() {
    int t = threadIdx.x;
    if (t < NE) { g_count[t] = 0; g_prob_sum[t] = 0.0f; }
}

// ---------------- router (proven round 1) ---------------------------------------
__global__ void router_kernel(const float* __restrict__ x,
                              const float* __restrict__ Wg,
                              const float* __restrict__ bg) {
    __shared__ float s_prob[NE];
    if (threadIdx.x < NE) s_prob[threadIdx.x] = 0.0f;
    __syncthreads();
    int warp = (blockIdx.x * blockDim.x + threadIdx.x) >> 5;
    int lane = threadIdx.x & 31;
    if (warp < T_TOK) {
        int t = warp;
        const float* xr = x + (size_t)t * DM;
        float acc[NE];
#pragma unroll
        for (int e = 0; e < NE; e++) acc[e] = 0.0f;
        for (int d = lane; d < DM; d += 32) {
            float xv = xr[d];
            const float* wr = Wg + d * NE;
#pragma unroll
            for (int e = 0; e < NE; e++) acc[e] += xv * wr[e];
        }
#pragma unroll
        for (int e = 0; e < NE; e++) {
            acc[e] += __shfl_down_sync(0xffffffffu, acc[e], 16);
            acc[e] += __shfl_down_sync(0xffffffffu, acc[e], 8);
            acc[e] += __shfl_down_sync(0xffffffffu, acc[e], 4);
            acc[e] += __shfl_down_sync(0xffffffffu, acc[e], 2);
            acc[e] += __shfl_down_sync(0xffffffffu, acc[e], 1);
        }
        if (lane == 0) {
            float p[NE], mx = -1e30f;
#pragma unroll
            for (int e = 0; e < NE; e++) { p[e] = acc[e] + bg[e]; mx = fmaxf(mx, p[e]); }
            float s = 0.0f;
#pragma unroll
            for (int e = 0; e < NE; e++) { p[e] = __expf(p[e] - mx); s += p[e]; }
            float inv = 1.0f / s;
#pragma unroll
            for (int e = 0; e < NE; e++) p[e] *= inv;
            int i0 = 0;
#pragma unroll
            for (int e = 1; e < NE; e++) if (p[e] > p[i0]) i0 = e;
            int i1 = (i0 == 0) ? 1 : 0;
#pragma unroll
            for (int e = 0; e < NE; e++) if (e != i0 && p[e] > p[i1]) i1 = e;
            float w0 = p[i0], w1 = p[i1];
            float winv = 1.0f / (w0 + w1);
            w0 *= winv; w1 *= winv;
            int s0 = atomicAdd(&g_count[i0], 1);
            int s1 = atomicAdd(&g_count[i1], 1);
            g_tok[i0 * T_TOK + s0] = t;
            g_tok[i1 * T_TOK + s1] = t;
            g_entry[t * 2 + 0] = i0 * T_TOK + s0;
            g_entry[t * 2 + 1] = i1 * T_TOK + s1;
            g_wgt[t * 2 + 0] = w0;
            g_wgt[t * 2 + 1] = w1;
#pragma unroll
            for (int e = 0; e < NE; e++) atomicAdd(&s_prob[e], p[e]);
        }
    }
    __syncthreads();
    if (threadIdx.x < NE) atomicAdd(&g_prob_sum[threadIdx.x], s_prob[threadIdx.x]);
}

// ---------------- wmma grouped GEMM with inline fp32->bf16 limb split -----------
// CTA tile 64(m) x 128(n), 8 warps (2m x 4n), warp tile 32x32, KC=32, 2 stages.
// A (fp32): MODE1 = gathered rows of x [T][DM]; MODE2 = dense rows of g_H.
// B (fp32): original weight layout [E][K][N], row-major wmma matrix_b.
// 3-limb: hi*hi + hi*lo + lo*hi.
#define KC 32
#define APITCH_B 96      // 64B bf16 data + 32B pad
#define BPITCH_B 288     // 256B bf16 data + 32B pad
#define AH_OFF 0
#define AL_OFF 6144
#define BH_OFF 12288
#define BL_OFF 21504
#define STG 30720
#define ROWS_OFF 61440
#define GEMM_SMEM 61696

template <int KTOT, int NTOT, int MODE>
__global__ __launch_bounds__(256)
void moe_gemm_kernel(const float* __restrict__ x,
                     const float* __restrict__ W,
                     const float* __restrict__ bias) {
    int e = blockIdx.z;
    int cnt = g_count[e];
    int m0 = blockIdx.y * 64;
    if (m0 >= cnt) return;
    int n0 = blockIdx.x * 128;

    extern __shared__ char smem[];
    int* rows = (int*)(smem + ROWS_OFF);
    int tid = threadIdx.x;
    int wid = tid >> 5, lane = tid & 31;
    int m_base = (wid >> 2) * 32;
    int n_base = (wid & 3) * 32;

    if (tid < 64) {
        int mi = m0 + tid;
        int ms = (mi < cnt) ? mi : (cnt - 1);
        rows[tid] = (MODE == 1) ? g_tok[e * T_TOK + ms] : (e * T_TOK + ms);
    }
    __syncthreads();

    // A source: MODE1 -> x (token rows), MODE2 -> g_H (expert rows)
    const float* Asrc = (MODE == 1) ? x : g_H;
    const float* Bsrc = W + (size_t)e * KTOT * NTOT;

    wmma::fragment<wmma::accumulator, 16, 16, 16, float> acc[2][2];
#pragma unroll
    for (int mt = 0; mt < 2; mt++)
#pragma unroll
        for (int nt = 0; nt < 2; nt++) wmma::fill_fragment(acc[mt][nt], 0.0f);

    auto load_stage = [&](int c, int s) {
        int k0 = c * KC;
        char* dst = smem + s * STG;
        {   // A: 64 rows x 32 fp32 -> hi/lo bf16; 256 slots of 8 elems
            int r = tid >> 2, q = tid & 3;
            const float* src = Asrc + (size_t)rows[r] * KTOT + k0 + q * 8;
            split8_store(src, dst + AH_OFF + r * APITCH_B + q * 16,
                              dst + AL_OFF + r * APITCH_B + q * 16);
        }
#pragma unroll
        for (int j = 0; j < 2; j++) {  // B: 32 k-rows x 128 n-cols; 512 slots
            int idx = tid + j * 256;
            int r = idx >> 4, q = idx & 15;
            const float* src = Bsrc + (size_t)(k0 + r) * NTOT + n0 + q * 8;
            split8_store(src, dst + BH_OFF + r * BPITCH_B + q * 16,
                              dst + BL_OFF + r * BPITCH_B + q * 16);
        }
    };

    const int NC = KTOT / KC;
    load_stage(0, 0);
    __syncthreads();

    const int AP = APITCH_B / 2;   // 48 elements
    const int BP = BPITCH_B / 2;   // 144 elements

    for (int c = 0; c < NC; c++) {
        int s = c & 1;
        if (c + 1 < NC) load_stage(c + 1, s ^ 1);

        const __nv_bfloat16* Ahs = (const __nv_bfloat16*)(smem + s * STG + AH_OFF);
        const __nv_bfloat16* Als = (const __nv_bfloat16*)(smem + s * STG + AL_OFF);
        const __nv_bfloat16* Bhs = (const __nv_bfloat16*)(smem + s * STG + BH_OFF);
        const __nv_bfloat16* Bls = (const __nv_bfloat16*)(smem + s * STG + BL_OFF);

#pragma unroll
        for (int ks = 0; ks < 2; ks++) {
            wmma::fragment<wmma::matrix_b, 16, 16, 16, __nv_bfloat16, wmma::row_major> bh[2], bl[2];
#pragma unroll
            for (int nt = 0; nt < 2; nt++) {
                wmma::load_matrix_sync(bh[nt], Bhs + ks * 16 * BP + n_base + nt * 16, BP);
                wmma::load_matrix_sync(bl[nt], Bls + ks * 16 * BP + n_base + nt * 16, BP);
            }
#pragma unroll
            for (int mt = 0; mt < 2; mt++) {
                wmma::fragment<wmma::matrix_a, 16, 16, 16, __nv_bfloat16, wmma::row_major> ah, al;
                wmma::load_matrix_sync(ah, Ahs + (m_base + mt * 16) * AP + ks * 16, AP);
                wmma::load_matrix_sync(al, Als + (m_base + mt * 16) * AP + ks * 16, AP);
#pragma unroll
                for (int nt = 0; nt < 2; nt++) {
                    wmma::mma_sync(acc[mt][nt], ah, bh[nt], acc[mt][nt]);
                    wmma::mma_sync(acc[mt][nt], ah, bl[nt], acc[mt][nt]);
                    wmma::mma_sync(acc[mt][nt], al, bh[nt], acc[mt][nt]);
                }
            }
        }
        __syncthreads();
    }

    // epilogue: per-warp scratch (smem free after last barrier), fp32 outputs
    float* scr = (float*)smem + wid * 256;
    const float* be = bias + (size_t)e * NTOT;
    int row = lane >> 1, c0l = (lane & 1) * 8;
#pragma unroll
    for (int mt = 0; mt < 2; mt++) {
#pragma unroll
        for (int nt = 0; nt < 2; nt++) {
            wmma::store_matrix_sync(scr, acc[mt][nt], 16, wmma::mem_row_major);
            __syncwarp();
            int mi = m0 + m_base + mt * 16 + row;
            int n = n0 + n_base + nt * 16 + c0l;
            if (mi < cnt) {
                size_t rowb = (size_t)e * T_TOK + mi;
                float v[8];
#pragma unroll
                for (int i = 0; i < 8; i++) v[i] = scr[row * 16 + c0l + i] + be[n + i];
                if (MODE == 1) {
#pragma unroll
                    for (int i = 0; i < 8; i++) v[i] = v[i] > 0.0f ? v[i] : 0.0f;
                    float4* d4 = (float4*)(g_H + rowb * DF + n);
                    d4[0] = make_float4(v[0], v[1], v[2], v[3]);
                    d4[1] = make_float4(v[4], v[5], v[6], v[7]);
                } else {
                    float4* d4 = (float4*)(g_Y + rowb * DM + n);
                    d4[0] = make_float4(v[0], v[1], v[2], v[3]);
                    d4[1] = make_float4(v[4], v[5], v[6], v[7]);
                }
            }
            __syncwarp();
        }
    }
}

// ---------------- combine (proven round 1) --------------------------------------
__global__ void combine_kernel(float* __restrict__ out) {
    int idx = blockIdx.x * blockDim.x + threadIdx.x;
    int total = T_TOK * (DM / 4);
    if (idx >= total) return;
    int t = idx / (DM / 4);
    int d4 = idx % (DM / 4);
    int e0 = g_entry[t * 2 + 0];
    int e1 = g_entry[t * 2 + 1];
    float w0 = g_wgt[t * 2 + 0];
    float w1 = g_wgt[t * 2 + 1];
    float4 a = ((const float4*)(g_Y + (size_t)e0 * DM))[d4];
    float4 b = ((const float4*)(g_Y + (size_t)e1 * DM))[d4];
    float4 o;
    o.x = w0 * a.x + w1 * b.x;
    o.y = w0 * a.y + w1 * b.y;
    o.z = w0 * a.z + w1 * b.z;
    o.w = w0 * a.w + w1 * b.w;
    ((float4*)out)[idx] = o;
}

// ---------------- loss (proven round 1) -----------------------------------------
__global__ void loss_kernel(float* __restrict__ out) {
    if (threadIdx.x == 0 && blockIdx.x == 0) {
        float m[NE], mu = 0.0f;
#pragma unroll
        for (int e = 0; e < NE; e++) { m[e] = g_prob_sum[e] / (float)T_TOK; mu += m[e]; }
        mu /= (float)NE;
        float v = 0.0f;
#pragma unroll
        for (int e = 0; e < NE; e++) { float d = m[e] - mu; v += d * d; }
        v /= (float)(NE - 1);
        out[(size_t)T_TOK * DM] = v;
    }
}

// ---------------- launch --------------------------------------------------------
extern "C" void kernel_launch(void* const* d_in, const int* in_sizes, int n_in,
                              void* d_out, int out_size) {
    const float* x  = (const float*)d_in[0];
    const float* Wg = (const float*)d_in[1];
    const float* bg = (const float*)d_in[2];
    const float* W1 = (const float*)d_in[3];
    const float* b1 = (const float*)d_in[4];
    const float* W2 = (const float*)d_in[5];
    const float* b2 = (const float*)d_in[6];
    float* out = (float*)d_out;

    cudaFuncSetAttribute(moe_gemm_kernel<DM, DF, 1>,
                         cudaFuncAttributeMaxDynamicSharedMemorySize, GEMM_SMEM);
    cudaFuncSetAttribute(moe_gemm_kernel<DF, DM, 2>,
                         cudaFuncAttributeMaxDynamicSharedMemorySize, GEMM_SMEM);

    init_kernel<<<1, 32>>>();
    router_kernel<<<T_TOK / 8, 256>>>(x, Wg, bg);

    moe_gemm_kernel<DM, DF, 1><<<dim3(DF / 128, T_TOK / 64, NE), 256, GEMM_SMEM>>>(x, W1, b1);
    moe_gemm_kernel<DF, DM, 2><<<dim3(DM / 128, T_TOK / 64, NE), 256, GEMM_SMEM>>>(g_H, W2, b2);

    combine_kernel<<<(T_TOK * (DM / 4) + 255) / 256, 256>>>(out);
    loss_kernel<<<1, 1>>>(out);
}

// round 8
// speedup vs baseline: 2.2788x; 1.1999x over previous
#include <cuda_runtime.h>
#include <cuda_bf16.h>
#include <mma.h>
#include <math.h>
#include <stdint.h>

using namespace nvcuda;

#define T_TOK 8192
#define DM 1024
#define DF 4096
#define NE 8

// ---------------- scratch (device globals; no allocation allowed) -------------
__device__ int   g_count[NE];
__device__ float g_prob_sum[NE];
__device__ int   g_tok[NE * T_TOK];
__device__ int   g_entry[T_TOK * 2];
__device__ float g_wgt[T_TOK * 2];
__device__ float g_H[(size_t)NE * T_TOK * DF];
__device__ float g_Y[(size_t)NE * T_TOK * DM];

// ---------------- helpers ------------------------------------------------------
__device__ __forceinline__ void split2(float v, __nv_bfloat16& h, __nv_bfloat16& l) {
    h = __float2bfloat16(v);
    l = __float2bfloat16(v - __bfloat162float(h));
}

__device__ __forceinline__ void split8_store(const float* __restrict__ src,
                                             char* dh, char* dl) {
    float4 v0 = *(const float4*)src;
    float4 v1 = *(const float4*)(src + 4);
    float vv[8] = {v0.x, v0.y, v0.z, v0.w, v1.x, v1.y, v1.z, v1.w};
    __align__(16) __nv_bfloat16 h[8];
    __align__(16) __nv_bfloat16 l[8];
#pragma unroll
    for (int i = 0; i < 8; i++) split2(vv[i], h[i], l[i]);
    *(uint4*)dh = *(const uint4*)h;
    *(uint4*)dl = *(const uint4*)l;
}

// ---------------- init ---------------------------------------------------------
__global__ void init_kernel() {
    int t = threadIdx.x;
    if (t < NE) { g_count[t] = 0; g_prob_sum[t] = 0.0f; }
}

// ---------------- router (proven) ----------------------------------------------
__global__ void router_kernel(const float* __restrict__ x,
                              const float* __restrict__ Wg,
                              const float* __restrict__ bg) {
    __shared__ float s_prob[NE];
    if (threadIdx.x < NE) s_prob[threadIdx.x] = 0.0f;
    __syncthreads();
    int warp = (blockIdx.x * blockDim.x + threadIdx.x) >> 5;
    int lane = threadIdx.x & 31;
    if (warp < T_TOK) {
        int t = warp;
        const float* xr = x + (size_t)t * DM;
        float acc[NE];
#pragma unroll
        for (int e = 0; e < NE; e++) acc[e] = 0.0f;
        for (int d = lane; d < DM; d += 32) {
            float xv = xr[d];
            const float* wr = Wg + d * NE;
#pragma unroll
            for (int e = 0; e < NE; e++) acc[e] += xv * wr[e];
        }
#pragma unroll
        for (int e = 0; e < NE; e++) {
            acc[e] += __shfl_down_sync(0xffffffffu, acc[e], 16);
            acc[e] += __shfl_down_sync(0xffffffffu, acc[e], 8);
            acc[e] += __shfl_down_sync(0xffffffffu, acc[e], 4);
            acc[e] += __shfl_down_sync(0xffffffffu, acc[e], 2);
            acc[e] += __shfl_down_sync(0xffffffffu, acc[e], 1);
        }
        if (lane == 0) {
            float p[NE], mx = -1e30f;
#pragma unroll
            for (int e = 0; e < NE; e++) { p[e] = acc[e] + bg[e]; mx = fmaxf(mx, p[e]); }
            float s = 0.0f;
#pragma unroll
            for (int e = 0; e < NE; e++) { p[e] = __expf(p[e] - mx); s += p[e]; }
            float inv = 1.0f / s;
#pragma unroll
            for (int e = 0; e < NE; e++) p[e] *= inv;
            int i0 = 0;
#pragma unroll
            for (int e = 1; e < NE; e++) if (p[e] > p[i0]) i0 = e;
            int i1 = (i0 == 0) ? 1 : 0;
#pragma unroll
            for (int e = 0; e < NE; e++) if (e != i0 && p[e] > p[i1]) i1 = e;
            float w0 = p[i0], w1 = p[i1];
            float winv = 1.0f / (w0 + w1);
            w0 *= winv; w1 *= winv;
            int s0 = atomicAdd(&g_count[i0], 1);
            int s1 = atomicAdd(&g_count[i1], 1);
            g_tok[i0 * T_TOK + s0] = t;
            g_tok[i1 * T_TOK + s1] = t;
            g_entry[t * 2 + 0] = i0 * T_TOK + s0;
            g_entry[t * 2 + 1] = i1 * T_TOK + s1;
            g_wgt[t * 2 + 0] = w0;
            g_wgt[t * 2 + 1] = w1;
#pragma unroll
            for (int e = 0; e < NE; e++) atomicAdd(&s_prob[e], p[e]);
        }
    }
    __syncthreads();
    if (threadIdx.x < NE) atomicAdd(&g_prob_sum[threadIdx.x], s_prob[threadIdx.x]);
}

// ---------------- wmma grouped GEMM with inline fp32->bf16 limb split -----------
// CTA tile 128(m) x 128(n), 8 warps (2m x 4n), warp tile 64x32, KC=32, 2 stages.
// Conflict-free pitches: A 80B (5x16B), B 272B (17x16B).
// 3-limb: hi*hi + hi*lo + lo*hi.
#define KC 32
#define APITCH_B 80
#define BPITCH_B 272
#define AH_OFF 0
#define AL_OFF 10240
#define BH_OFF 20480
#define BL_OFF 29184
#define STG 37888
#define ROWS_OFF 75776
#define GEMM_SMEM 76288

template <int KTOT, int NTOT, int MODE>
__global__ __launch_bounds__(256)
void moe_gemm_kernel(const float* __restrict__ x,
                     const float* __restrict__ W,
                     const float* __restrict__ bias) {
    int e = blockIdx.z;
    int cnt = g_count[e];
    int m0 = blockIdx.y * 128;
    if (m0 >= cnt) return;
    int n0 = blockIdx.x * 128;

    extern __shared__ char smem[];
    int* rows = (int*)(smem + ROWS_OFF);
    int tid = threadIdx.x;
    int wid = tid >> 5, lane = tid & 31;
    int m_base = (wid >> 2) * 64;
    int n_base = (wid & 3) * 32;

    if (tid < 128) {
        int mi = m0 + tid;
        int ms = (mi < cnt) ? mi : (cnt - 1);
        rows[tid] = (MODE == 1) ? g_tok[e * T_TOK + ms] : (e * T_TOK + ms);
    }
    __syncthreads();

    const float* Asrc = (MODE == 1) ? x : g_H;
    const float* Bsrc = W + (size_t)e * KTOT * NTOT;

    wmma::fragment<wmma::accumulator, 16, 16, 16, float> acc[4][2];
#pragma unroll
    for (int mt = 0; mt < 4; mt++)
#pragma unroll
        for (int nt = 0; nt < 2; nt++) wmma::fill_fragment(acc[mt][nt], 0.0f);

    auto load_stage = [&](int c, int s) {
        int k0 = c * KC;
        char* dst = smem + s * STG;
#pragma unroll
        for (int j = 0; j < 2; j++) {  // A: 128 rows x 4 quads = 512 slots
            int idx = tid + j * 256;
            int r = idx >> 2, q = idx & 3;
            const float* src = Asrc + (size_t)rows[r] * KTOT + k0 + q * 8;
            split8_store(src, dst + AH_OFF + r * APITCH_B + q * 16,
                              dst + AL_OFF + r * APITCH_B + q * 16);
        }
#pragma unroll
        for (int j = 0; j < 2; j++) {  // B: 32 k-rows x 16 quads = 512 slots
            int idx = tid + j * 256;
            int r = idx >> 4, q = idx & 15;
            const float* src = Bsrc + (size_t)(k0 + r) * NTOT + n0 + q * 8;
            split8_store(src, dst + BH_OFF + r * BPITCH_B + q * 16,
                              dst + BL_OFF + r * BPITCH_B + q * 16);
        }
    };

    const int NC = KTOT / KC;
    load_stage(0, 0);
    __syncthreads();

    const int AP = APITCH_B / 2;   // 40 elements
    const int BP = BPITCH_B / 2;   // 136 elements

    for (int c = 0; c < NC; c++) {
        int s = c & 1;
        if (c + 1 < NC) load_stage(c + 1, s ^ 1);

        const __nv_bfloat16* Ahs = (const __nv_bfloat16*)(smem + s * STG + AH_OFF);
        const __nv_bfloat16* Als = (const __nv_bfloat16*)(smem + s * STG + AL_OFF);
        const __nv_bfloat16* Bhs = (const __nv_bfloat16*)(smem + s * STG + BH_OFF);
        const __nv_bfloat16* Bls = (const __nv_bfloat16*)(smem + s * STG + BL_OFF);

#pragma unroll
        for (int ks = 0; ks < 2; ks++) {
            wmma::fragment<wmma::matrix_b, 16, 16, 16, __nv_bfloat16, wmma::row_major> bh[2], bl[2];
#pragma unroll
            for (int nt = 0; nt < 2; nt++) {
                wmma::load_matrix_sync(bh[nt], Bhs + ks * 16 * BP + n_base + nt * 16, BP);
                wmma::load_matrix_sync(bl[nt], Bls + ks * 16 * BP + n_base + nt * 16, BP);
            }
#pragma unroll
            for (int mt = 0; mt < 4; mt++) {
                wmma::fragment<wmma::matrix_a, 16, 16, 16, __nv_bfloat16, wmma::row_major> ah, al;
                wmma::load_matrix_sync(ah, Ahs + (m_base + mt * 16) * AP + ks * 16, AP);
                wmma::load_matrix_sync(al, Als + (m_base + mt * 16) * AP + ks * 16, AP);
#pragma unroll
                for (int nt = 0; nt < 2; nt++) {
                    wmma::mma_sync(acc[mt][nt], ah, bh[nt], acc[mt][nt]);
                    wmma::mma_sync(acc[mt][nt], ah, bl[nt], acc[mt][nt]);
                    wmma::mma_sync(acc[mt][nt], al, bh[nt], acc[mt][nt]);
                }
            }
        }
        __syncthreads();
    }

    // epilogue: per-warp scratch (smem free after last barrier), fp32 outputs
    float* scr = (float*)smem + wid * 256;
    const float* be = bias + (size_t)e * NTOT;
    int row = lane >> 1, c0l = (lane & 1) * 8;
#pragma unroll
    for (int mt = 0; mt < 4; mt++) {
#pragma unroll
        for (int nt = 0; nt < 2; nt++) {
            wmma::store_matrix_sync(scr, acc[mt][nt], 16, wmma::mem_row_major);
            __syncwarp();
            int mi = m0 + m_base + mt * 16 + row;
            int n = n0 + n_base + nt * 16 + c0l;
            if (mi < cnt) {
                size_t rowb = (size_t)e * T_TOK + mi;
                float v[8];
#pragma unroll
                for (int i = 0; i < 8; i++) v[i] = scr[row * 16 + c0l + i] + be[n + i];
                if (MODE == 1) {
#pragma unroll
                    for (int i = 0; i < 8; i++) v[i] = v[i] > 0.0f ? v[i] : 0.0f;
                    float4* d4 = (float4*)(g_H + rowb * DF + n);
                    d4[0] = make_float4(v[0], v[1], v[2], v[3]);
                    d4[1] = make_float4(v[4], v[5], v[6], v[7]);
                } else {
                    float4* d4 = (float4*)(g_Y + rowb * DM + n);
                    d4[0] = make_float4(v[0], v[1], v[2], v[3]);
                    d4[1] = make_float4(v[4], v[5], v[6], v[7]);
                }
            }
            __syncwarp();
        }
    }
}

// ---------------- combine (proven) ---------------------------------------------
__global__ void combine_kernel(float* __restrict__ out) {
    int idx = blockIdx.x * blockDim.x + threadIdx.x;
    int total = T_TOK * (DM / 4);
    if (idx >= total) return;
    int t = idx / (DM / 4);
    int d4 = idx % (DM / 4);
    int e0 = g_entry[t * 2 + 0];
    int e1 = g_entry[t * 2 + 1];
    float w0 = g_wgt[t * 2 + 0];
    float w1 = g_wgt[t * 2 + 1];
    float4 a = ((const float4*)(g_Y + (size_t)e0 * DM))[d4];
    float4 b = ((const float4*)(g_Y + (size_t)e1 * DM))[d4];
    float4 o;
    o.x = w0 * a.x + w1 * b.x;
    o.y = w0 * a.y + w1 * b.y;
    o.z = w0 * a.z + w1 * b.z;
    o.w = w0 * a.w + w1 * b.w;
    ((float4*)out)[idx] = o;
}

// ---------------- loss (proven) -------------------------------------------------
__global__ void loss_kernel(float* __restrict__ out) {
    if (threadIdx.x == 0 && blockIdx.x == 0) {
        float m[NE], mu = 0.0f;
#pragma unroll
        for (int e = 0; e < NE; e++) { m[e] = g_prob_sum[e] / (float)T_TOK; mu += m[e]; }
        mu /= (float)NE;
        float v = 0.0f;
#pragma unroll
        for (int e = 0; e < NE; e++) { float d = m[e] - mu; v += d * d; }
        v /= (float)(NE - 1);
        out[(size_t)T_TOK * DM] = v;
    }
}

// ---------------- launch --------------------------------------------------------
extern "C" void kernel_launch(void* const* d_in, const int* in_sizes, int n_in,
                              void* d_out, int out_size) {
    const float* x  = (const float*)d_in[0];
    const float* Wg = (const float*)d_in[1];
    const float* bg = (const float*)d_in[2];
    const float* W1 = (const float*)d_in[3];
    const float* b1 = (const float*)d_in[4];
    const float* W2 = (const float*)d_in[5];
    const float* b2 = (const float*)d_in[6];
    float* out = (float*)d_out;

    cudaFuncSetAttribute(moe_gemm_kernel<DM, DF, 1>,
                         cudaFuncAttributeMaxDynamicSharedMemorySize, GEMM_SMEM);
    cudaFuncSetAttribute(moe_gemm_kernel<DF, DM, 2>,
                         cudaFuncAttributeMaxDynamicSharedMemorySize, GEMM_SMEM);

    init_kernel<<<1, 32>>>();
    router_kernel<<<T_TOK / 8, 256>>>(x, Wg, bg);

    moe_gemm_kernel<DM, DF, 1><<<dim3(DF / 128, T_TOK / 128, NE), 256, GEMM_SMEM>>>(x, W1, b1);
    moe_gemm_kernel<DF, DM, 2><<<dim3(DM / 128, T_TOK / 128, NE), 256, GEMM_SMEM>>>(g_H, W2, b2);

    combine_kernel<<<(T_TOK * (DM / 4) + 255) / 256, 256>>>(out);
    loss_kernel<<<1, 1>>>(out);
}

// round 9
// speedup vs baseline: 2.4049x; 1.0553x over previous
#include <cuda_runtime.h>
#include <cuda_bf16.h>
#include <mma.h>
#include <math.h>
#include <stdint.h>

using namespace nvcuda;

#define T_TOK 8192
#define DM 1024
#define DF 4096
#define NE 8

// ---------------- scratch (device globals; no allocation allowed) -------------
__device__ int   g_count[NE];
__device__ float g_prob_sum[NE];
__device__ int   g_tok[NE * T_TOK];
__device__ int   g_entry[T_TOK * 2];
__device__ float g_wgt[T_TOK * 2];
__device__ float g_H[(size_t)NE * T_TOK * DF];
__device__ float g_Y[(size_t)NE * T_TOK * DM];

// ---------------- helpers ------------------------------------------------------
__device__ __forceinline__ void split2(float v, __nv_bfloat16& h, __nv_bfloat16& l) {
    h = __float2bfloat16(v);
    l = __float2bfloat16(v - __bfloat162float(h));
}

__device__ __forceinline__ void split8_store_reg(const float4& v0, const float4& v1,
                                                 char* dh, char* dl) {
    float vv[8] = {v0.x, v0.y, v0.z, v0.w, v1.x, v1.y, v1.z, v1.w};
    __align__(16) __nv_bfloat16 h[8];
    __align__(16) __nv_bfloat16 l[8];
#pragma unroll
    for (int i = 0; i < 8; i++) split2(vv[i], h[i], l[i]);
    *(uint4*)dh = *(const uint4*)h;
    *(uint4*)dl = *(const uint4*)l;
}

// ---------------- init ---------------------------------------------------------
__global__ void init_kernel() {
    int t = threadIdx.x;
    if (t < NE) { g_count[t] = 0; g_prob_sum[t] = 0.0f; }
}

// ---------------- router (proven) ----------------------------------------------
__global__ void router_kernel(const float* __restrict__ x,
                              const float* __restrict__ Wg,
                              const float* __restrict__ bg) {
    __shared__ float s_prob[NE];
    if (threadIdx.x < NE) s_prob[threadIdx.x] = 0.0f;
    __syncthreads();
    int warp = (blockIdx.x * blockDim.x + threadIdx.x) >> 5;
    int lane = threadIdx.x & 31;
    if (warp < T_TOK) {
        int t = warp;
        const float* xr = x + (size_t)t * DM;
        float acc[NE];
#pragma unroll
        for (int e = 0; e < NE; e++) acc[e] = 0.0f;
        for (int d = lane; d < DM; d += 32) {
            float xv = xr[d];
            const float* wr = Wg + d * NE;
#pragma unroll
            for (int e = 0; e < NE; e++) acc[e] += xv * wr[e];
        }
#pragma unroll
        for (int e = 0; e < NE; e++) {
            acc[e] += __shfl_down_sync(0xffffffffu, acc[e], 16);
            acc[e] += __shfl_down_sync(0xffffffffu, acc[e], 8);
            acc[e] += __shfl_down_sync(0xffffffffu, acc[e], 4);
            acc[e] += __shfl_down_sync(0xffffffffu, acc[e], 2);
            acc[e] += __shfl_down_sync(0xffffffffu, acc[e], 1);
        }
        if (lane == 0) {
            float p[NE], mx = -1e30f;
#pragma unroll
            for (int e = 0; e < NE; e++) { p[e] = acc[e] + bg[e]; mx = fmaxf(mx, p[e]); }
            float s = 0.0f;
#pragma unroll
            for (int e = 0; e < NE; e++) { p[e] = __expf(p[e] - mx); s += p[e]; }
            float inv = 1.0f / s;
#pragma unroll
            for (int e = 0; e < NE; e++) p[e] *= inv;
            int i0 = 0;
#pragma unroll
            for (int e = 1; e < NE; e++) if (p[e] > p[i0]) i0 = e;
            int i1 = (i0 == 0) ? 1 : 0;
#pragma unroll
            for (int e = 0; e < NE; e++) if (e != i0 && p[e] > p[i1]) i1 = e;
            float w0 = p[i0], w1 = p[i1];
            float winv = 1.0f / (w0 + w1);
            w0 *= winv; w1 *= winv;
            int s0 = atomicAdd(&g_count[i0], 1);
            int s1 = atomicAdd(&g_count[i1], 1);
            g_tok[i0 * T_TOK + s0] = t;
            g_tok[i1 * T_TOK + s1] = t;
            g_entry[t * 2 + 0] = i0 * T_TOK + s0;
            g_entry[t * 2 + 1] = i1 * T_TOK + s1;
            g_wgt[t * 2 + 0] = w0;
            g_wgt[t * 2 + 1] = w1;
#pragma unroll
            for (int e = 0; e < NE; e++) atomicAdd(&s_prob[e], p[e]);
        }
    }
    __syncthreads();
    if (threadIdx.x < NE) atomicAdd(&g_prob_sum[threadIdx.x], s_prob[threadIdx.x]);
}

// ---------------- wmma grouped GEMM, register-pipelined stage loads -------------
// CTA tile 128x128, 8 warps (2m x 4n), warp tile 64x32, KC=32, 2 smem stages.
// Pipeline: ldg(c+2) issued one full MMA iteration before its sts -> latency hidden.
// Conflict-free pitches: A 80B (5x16B), B 272B (17x16B).
// 3-limb: hi*hi + hi*lo + lo*hi.
#define KC 32
#define APITCH_B 80
#define BPITCH_B 272
#define AH_OFF 0
#define AL_OFF 10240
#define BH_OFF 20480
#define BL_OFF 29184
#define STG 37888
#define ROWS_OFF 75776
#define GEMM_SMEM 76288

template <int KTOT, int NTOT, int MODE>
__global__ __launch_bounds__(256)
void moe_gemm_kernel(const float* __restrict__ x,
                     const float* __restrict__ W,
                     const float* __restrict__ bias) {
    int e = blockIdx.z;
    int cnt = g_count[e];
    int m0 = blockIdx.y * 128;
    if (m0 >= cnt) return;
    int n0 = blockIdx.x * 128;

    extern __shared__ char smem[];
    int* rows = (int*)(smem + ROWS_OFF);
    int tid = threadIdx.x;
    int wid = tid >> 5, lane = tid & 31;
    int m_base = (wid >> 2) * 64;
    int n_base = (wid & 3) * 32;

    if (tid < 128) {
        int mi = m0 + tid;
        int ms = (mi < cnt) ? mi : (cnt - 1);
        rows[tid] = (MODE == 1) ? g_tok[e * T_TOK + ms] : (e * T_TOK + ms);
    }
    __syncthreads();

    const float* Asrc = (MODE == 1) ? x : g_H;
    const float* Bsrc = W + (size_t)e * KTOT * NTOT;

    // per-thread slot coordinates (fixed across iterations)
    int ar0 = tid >> 2,          aq0 = tid & 3;
    int ar1 = (tid + 256) >> 2,  aq1 = (tid + 256) & 3;
    int br0 = tid >> 4,          bq0 = tid & 15;
    int br1 = (tid + 256) >> 4,  bq1 = (tid + 256) & 15;

    float4 apf[2][2], bpf[2][2];

    auto ldg_stage = [&](int c) {
        int k0 = c * KC;
        {
            const float* s0 = Asrc + (size_t)rows[ar0] * KTOT + k0 + aq0 * 8;
            apf[0][0] = *(const float4*)s0;
            apf[0][1] = *(const float4*)(s0 + 4);
            const float* s1 = Asrc + (size_t)rows[ar1] * KTOT + k0 + aq1 * 8;
            apf[1][0] = *(const float4*)s1;
            apf[1][1] = *(const float4*)(s1 + 4);
        }
        {
            const float* s0 = Bsrc + (size_t)(k0 + br0) * NTOT + n0 + bq0 * 8;
            bpf[0][0] = *(const float4*)s0;
            bpf[0][1] = *(const float4*)(s0 + 4);
            const float* s1 = Bsrc + (size_t)(k0 + br1) * NTOT + n0 + bq1 * 8;
            bpf[1][0] = *(const float4*)s1;
            bpf[1][1] = *(const float4*)(s1 + 4);
        }
    };
    auto sts_stage = [&](int s) {
        char* dst = smem + s * STG;
        split8_store_reg(apf[0][0], apf[0][1],
                         dst + AH_OFF + ar0 * APITCH_B + aq0 * 16,
                         dst + AL_OFF + ar0 * APITCH_B + aq0 * 16);
        split8_store_reg(apf[1][0], apf[1][1],
                         dst + AH_OFF + ar1 * APITCH_B + aq1 * 16,
                         dst + AL_OFF + ar1 * APITCH_B + aq1 * 16);
        split8_store_reg(bpf[0][0], bpf[0][1],
                         dst + BH_OFF + br0 * BPITCH_B + bq0 * 16,
                         dst + BL_OFF + br0 * BPITCH_B + bq0 * 16);
        split8_store_reg(bpf[1][0], bpf[1][1],
                         dst + BH_OFF + br1 * BPITCH_B + bq1 * 16,
                         dst + BL_OFF + br1 * BPITCH_B + bq1 * 16);
    };

    wmma::fragment<wmma::accumulator, 16, 16, 16, float> acc[4][2];
#pragma unroll
    for (int mt = 0; mt < 4; mt++)
#pragma unroll
        for (int nt = 0; nt < 2; nt++) wmma::fill_fragment(acc[mt][nt], 0.0f);

    const int NC = KTOT / KC;
    ldg_stage(0);
    sts_stage(0);
    if (NC > 1) ldg_stage(1);
    __syncthreads();

    const int AP = APITCH_B / 2;   // 40 elements
    const int BP = BPITCH_B / 2;   // 136 elements

    for (int c = 0; c < NC; c++) {
        int s = c & 1;
        const __nv_bfloat16* Ahs = (const __nv_bfloat16*)(smem + s * STG + AH_OFF);
        const __nv_bfloat16* Als = (const __nv_bfloat16*)(smem + s * STG + AL_OFF);
        const __nv_bfloat16* Bhs = (const __nv_bfloat16*)(smem + s * STG + BH_OFF);
        const __nv_bfloat16* Bls = (const __nv_bfloat16*)(smem + s * STG + BL_OFF);

#pragma unroll
        for (int ks = 0; ks < 2; ks++) {
            wmma::fragment<wmma::matrix_b, 16, 16, 16, __nv_bfloat16, wmma::row_major> bh[2], bl[2];
#pragma unroll
            for (int nt = 0; nt < 2; nt++) {
                wmma::load_matrix_sync(bh[nt], Bhs + ks * 16 * BP + n_base + nt * 16, BP);
                wmma::load_matrix_sync(bl[nt], Bls + ks * 16 * BP + n_base + nt * 16, BP);
            }
#pragma unroll
            for (int mt = 0; mt < 4; mt++) {
                wmma::fragment<wmma::matrix_a, 16, 16, 16, __nv_bfloat16, wmma::row_major> ah, al;
                wmma::load_matrix_sync(ah, Ahs + (m_base + mt * 16) * AP + ks * 16, AP);
                wmma::load_matrix_sync(al, Als + (m_base + mt * 16) * AP + ks * 16, AP);
#pragma unroll
                for (int nt = 0; nt < 2; nt++) {
                    wmma::mma_sync(acc[mt][nt], ah, bh[nt], acc[mt][nt]);
                    wmma::mma_sync(acc[mt][nt], ah, bl[nt], acc[mt][nt]);
                    wmma::mma_sync(acc[mt][nt], al, bh[nt], acc[mt][nt]);
                }
            }
        }

        // regs hold stage c+1 (loaded one full iteration ago): store, then fetch c+2
        if (c + 1 < NC) sts_stage(s ^ 1);
        if (c + 2 < NC) ldg_stage(c + 2);
        __syncthreads();
    }

    // epilogue: per-warp scratch (smem free after last barrier), fp32 outputs
    float* scr = (float*)smem + wid * 256;
    const float* be = bias + (size_t)e * NTOT;
    int row = lane >> 1, c0l = (lane & 1) * 8;
#pragma unroll
    for (int mt = 0; mt < 4; mt++) {
#pragma unroll
        for (int nt = 0; nt < 2; nt++) {
            wmma::store_matrix_sync(scr, acc[mt][nt], 16, wmma::mem_row_major);
            __syncwarp();
            int mi = m0 + m_base + mt * 16 + row;
            int n = n0 + n_base + nt * 16 + c0l;
            if (mi < cnt) {
                size_t rowb = (size_t)e * T_TOK + mi;
                float v[8];
#pragma unroll
                for (int i = 0; i < 8; i++) v[i] = scr[row * 16 + c0l + i] + be[n + i];
                if (MODE == 1) {
#pragma unroll
                    for (int i = 0; i < 8; i++) v[i] = v[i] > 0.0f ? v[i] : 0.0f;
                    float4* d4 = (float4*)(g_H + rowb * DF + n);
                    d4[0] = make_float4(v[0], v[1], v[2], v[3]);
                    d4[1] = make_float4(v[4], v[5], v[6], v[7]);
                } else {
                    float4* d4 = (float4*)(g_Y + rowb * DM + n);
                    d4[0] = make_float4(v[0], v[1], v[2], v[3]);
                    d4[1] = make_float4(v[4], v[5], v[6], v[7]);
                }
            }
            __syncwarp();
        }
    }
}

// ---------------- combine (proven) ---------------------------------------------
__global__ void combine_kernel(float* __restrict__ out) {
    int idx = blockIdx.x * blockDim.x + threadIdx.x;
    int total = T_TOK * (DM / 4);
    if (idx >= total) return;
    int t = idx / (DM / 4);
    int d4 = idx % (DM / 4);
    int e0 = g_entry[t * 2 + 0];
    int e1 = g_entry[t * 2 + 1];
    float w0 = g_wgt[t * 2 + 0];
    float w1 = g_wgt[t * 2 + 1];
    float4 a = ((const float4*)(g_Y + (size_t)e0 * DM))[d4];
    float4 b = ((const float4*)(g_Y + (size_t)e1 * DM))[d4];
    float4 o;
    o.x = w0 * a.x + w1 * b.x;
    o.y = w0 * a.y + w1 * b.y;
    o.z = w0 * a.z + w1 * b.z;
    o.w = w0 * a.w + w1 * b.w;
    ((float4*)out)[idx] = o;
}

// ---------------- loss (proven) -------------------------------------------------
__global__ void loss_kernel(float* __restrict__ out) {
    if (threadIdx.x == 0 && blockIdx.x == 0) {
        float m[NE], mu = 0.0f;
#pragma unroll
        for (int e = 0; e < NE; e++) { m[e] = g_prob_sum[e] / (float)T_TOK; mu += m[e]; }
        mu /= (float)NE;
        float v = 0.0f;
#pragma unroll
        for (int e = 0; e < NE; e++) { float d = m[e] - mu; v += d * d; }
        v /= (float)(NE - 1);
        out[(size_t)T_TOK * DM] = v;
    }
}

// ---------------- launch --------------------------------------------------------
extern "C" void kernel_launch(void* const* d_in, const int* in_sizes, int n_in,
                              void* d_out, int out_size) {
    const float* x  = (const float*)d_in[0];
    const float* Wg = (const float*)d_in[1];
    const float* bg = (const float*)d_in[2];
    const float* W1 = (const float*)d_in[3];
    const float* b1 = (const float*)d_in[4];
    const float* W2 = (const float*)d_in[5];
    const float* b2 = (const float*)d_in[6];
    float* out = (float*)d_out;

    cudaFuncSetAttribute(moe_gemm_kernel<DM, DF, 1>,
                         cudaFuncAttributeMaxDynamicSharedMemorySize, GEMM_SMEM);
    cudaFuncSetAttribute(moe_gemm_kernel<DF, DM, 2>,
                         cudaFuncAttributeMaxDynamicSharedMemorySize, GEMM_SMEM);

    init_kernel<<<1, 32>>>();
    router_kernel<<<T_TOK / 8, 256>>>(x, Wg, bg);

    moe_gemm_kernel<DM, DF, 1><<<dim3(DF / 128, T_TOK / 128, NE), 256, GEMM_SMEM>>>(x, W1, b1);
    moe_gemm_kernel<DF, DM, 2><<<dim3(DM / 128, T_TOK / 128, NE), 256, GEMM_SMEM>>>(g_H, W2, b2);

    combine_kernel<<<(T_TOK * (DM / 4) + 255) / 256, 256>>>(out);
    loss_kernel<<<1, 1>>>(out);
}